// round 16
// baseline (speedup 1.0000x reference)
#include <cuda_runtime.h>
#include <cuda_bf16.h>
#include <stdint.h>
#include <stddef.h>

// Problem constants
#define B_   32
#define T_   4
#define D_   2048
#define H_   16
#define G_   4
#define K_   128
#define S_   4096
#define NREP 4
#define NS   7            // sequence splits for attention (49 chunks / 7 = balanced)
#define QKV_SPLITK 8
#define SCALE_ 0.08838834764831845f   // K^-0.5
#define EPS_   1e-6f

// ---------------- device scratch (no allocations allowed) ----------------
__device__ __align__(16) float g_qkvp[QKV_SPLITK * 128 * 3072];  // QKV split-K partials
__device__ __align__(16) float g_wop [8 * 128 * 2048];  // Wo split-K partials
__device__ __align__(16) float g_q  [128 * H_ * K_];    // post norm+rope
__device__ __align__(16) float g_kn [128 * G_ * K_];    // new K rows
__device__ __align__(16) float g_vn [128 * G_ * K_];    // new V rows
__device__ __align__(16) float g_attn[128 * H_ * K_];   // attention out
__device__ float g_ropes[128 * 64];                     // rope sin table [m][j]
__device__ float g_ropec[128 * 64];                     // rope cos table [m][j]
// split-attention partials
__device__ __align__(16) float g_pacc[B_ * G_ * NS * 16 * 128];
__device__ float g_pm  [B_ * G_ * NS * 16];
__device__ float g_pl  [B_ * G_ * NS * 16];

// ---------------- cp.async helpers ----------------
__device__ __forceinline__ void cp_async16(uint32_t dst, const void* src, bool p) {
    asm volatile("cp.async.cg.shared.global [%0], [%1], 16, %2;\n"
                 :: "r"(dst), "l"(src), "r"(p ? 16 : 0));
}
__device__ __forceinline__ void cp_commit() {
    asm volatile("cp.async.commit_group;\n" ::);
}
template<int N> __device__ __forceinline__ void cp_wait() {
    asm volatile("cp.async.wait_group %0;\n" :: "n"(N));
}

// ---------------- tf32 mma helpers ----------------
__device__ __forceinline__ uint32_t cvt_tf32(float x) {
    uint32_t u;
    asm("cvt.rna.tf32.f32 %0, %1;" : "=r"(u) : "f"(x));
    return u;
}
__device__ __forceinline__ void mma_tf32(float c[4],
    uint32_t a0, uint32_t a1, uint32_t a2, uint32_t a3,
    uint32_t b0, uint32_t b1)
{
    asm volatile(
        "mma.sync.aligned.m16n8k8.row.col.f32.tf32.tf32.f32 "
        "{%0,%1,%2,%3}, {%4,%5,%6,%7}, {%8,%9}, {%0,%1,%2,%3};\n"
        : "+f"(c[0]), "+f"(c[1]), "+f"(c[2]), "+f"(c[3])
        : "r"(a0), "r"(a1), "r"(a2), "r"(a3), "r"(b0), "r"(b1));
}

// ---------------- K0: rope sin/cos table (identical math to reference) ------
__global__ void rope_table_kernel(const int* __restrict__ seg,
                                  const int* __restrict__ curp)
{
    int idx = blockIdx.x * 256 + threadIdx.x;   // 0..8191
    if (idx >= 128 * 64) return;
    int m = idx >> 6;
    int j = idx & 63;

    int bb = m >> 2, tt = m & 3;
    int csum = 0;
    #pragma unroll
    for (int t = 0; t < T_; t++)
        if (t <= tt) csum += (seg[bb * T_ + t] != 0) ? 1 : 0;
    int pos = csum - 1 + *curp;

    float fr  = (float)j * (1.0f / 64.0f);
    float ts  = powf(10000.0f, fr);        // accurate pow (matches reference)
    float ang = (float)pos / ts;
    float sv, cv;
    sincosf(ang, &sv, &cv);
    g_ropes[idx] = sv;
    g_ropec[idx] = cv;
}

// ---------------- GEMM: tf32 mma, 64x64 tile, split-K via blockIdx.z ---------
template<int KIT>
__global__ __launch_bounds__(128) void mma_gemm_kernel(
    const float* __restrict__ A_,
    const float* __restrict__ W0, const float* __restrict__ W1,
    const float* __restrict__ W2,
    int ldc, int qkv)
{
    __shared__ alignas(16) float As[4][64][20];   // [buf][m][k], stride 20
    __shared__ alignas(16) float Ws[4][16][72];   // [buf][k][n], stride 72

    const float* A = qkv ? A_ : (const float*)g_attn;
    float*       C = qkv ? (g_qkvp + (size_t)blockIdx.z * 128 * 3072)
                         : (g_wop  + (size_t)blockIdx.z * 128 * 2048);
    int kbase = blockIdx.z * KIT;

    int c0 = blockIdx.x * 64;
    const float* W; int ldb, cb;
    if (qkv) {
        if (c0 < 2048)      { W = W0; ldb = 2048; cb = c0; }
        else if (c0 < 2560) { W = W1; ldb = 512;  cb = c0 - 2048; }
        else                { W = W2; ldb = 512;  cb = c0 - 2560; }
    } else                  { W = W0; ldb = 2048; cb = c0; }

    int m0   = blockIdx.y * 64;
    int tid  = threadIdx.x;           // 128
    int wid  = tid >> 5;
    int lane = tid & 31;
    int gq   = lane >> 2;             // group id 0..7
    int tg   = lane & 3;              // thread-in-group 0..3
    int wm0  = (wid >> 1) << 5;       // warp m offset 0/32
    int wn0  = (wid & 1) << 5;        // warp n offset 0/32

    uint32_t sAs = (uint32_t)__cvta_generic_to_shared(&As[0][0][0]);
    uint32_t sWs = (uint32_t)__cvta_generic_to_shared(&Ws[0][0][0]);

    auto issue = [&](int it, int buf) {
        int k0 = (kbase + it) << 4;
        #pragma unroll
        for (int j = 0; j < 2; j++) {                // A: 64 rows x 16 cols
            int idx = tid + (j << 7);                // 0..255 float4
            int row = idx >> 2, q = (idx & 3) << 2;
            cp_async16(sAs + (uint32_t)(buf * 1280 + row * 20 + q) * 4,
                       A + (size_t)(m0 + row) * 2048 + k0 + q, true);
        }
        #pragma unroll
        for (int j = 0; j < 2; j++) {                // W: 16 rows x 64 cols
            int idx = tid + (j << 7);                // 0..255 float4
            int row = idx >> 4, q = (idx & 15) << 2;
            cp_async16(sWs + (uint32_t)(buf * 1152 + row * 72 + q) * 4,
                       W + (size_t)(k0 + row) * ldb + cb + q, true);
        }
    };

    float c[2][4][4];
    #pragma unroll
    for (int mb = 0; mb < 2; mb++)
        #pragma unroll
        for (int nb = 0; nb < 4; nb++)
            #pragma unroll
            for (int j = 0; j < 4; j++) c[mb][nb][j] = 0.f;

    issue(0, 0); cp_commit();
    issue(1, 1); cp_commit();
    issue(2, 2); cp_commit();

    for (int it = 0; it < KIT; it++) {
        int bf = it & 3;
        cp_wait<2>();
        __syncthreads();

        #pragma unroll
        for (int kk = 0; kk < 16; kk += 8) {
            uint32_t a[2][4], bfr[4][2];
            #pragma unroll
            for (int mb = 0; mb < 2; mb++) {
                int r0 = wm0 + (mb << 4) + gq;
                a[mb][0] = cvt_tf32(As[bf][r0    ][kk + tg]);
                a[mb][1] = cvt_tf32(As[bf][r0 + 8][kk + tg]);
                a[mb][2] = cvt_tf32(As[bf][r0    ][kk + tg + 4]);
                a[mb][3] = cvt_tf32(As[bf][r0 + 8][kk + tg + 4]);
            }
            #pragma unroll
            for (int nb = 0; nb < 4; nb++) {
                int cn = wn0 + (nb << 3) + gq;
                bfr[nb][0] = cvt_tf32(Ws[bf][kk + tg    ][cn]);
                bfr[nb][1] = cvt_tf32(Ws[bf][kk + tg + 4][cn]);
            }
            #pragma unroll
            for (int mb = 0; mb < 2; mb++)
                #pragma unroll
                for (int nb = 0; nb < 4; nb++)
                    mma_tf32(c[mb][nb], a[mb][0], a[mb][1], a[mb][2], a[mb][3],
                             bfr[nb][0], bfr[nb][1]);
        }
        __syncthreads();
        if (it + 3 < KIT) issue(it + 3, (it + 3) & 3);
        cp_commit();
    }

    #pragma unroll
    for (int mb = 0; mb < 2; mb++)
        #pragma unroll
        for (int nb = 0; nb < 4; nb++) {
            int row = m0 + wm0 + (mb << 4) + gq;
            int col = c0 + wn0 + (nb << 3) + (tg << 1);
            *(float2*)(C + (size_t)row * ldc + col)
                = make_float2(c[mb][nb][0], c[mb][nb][1]);
            *(float2*)(C + (size_t)(row + 8) * ldc + col)
                = make_float2(c[mb][nb][2], c[mb][nb][3]);
        }
}

// ---------------- Wo split-K reduce: d_out = sum of 8 partials ----------------
__global__ void wo_reduce_kernel(float* __restrict__ out) {
    int idx = (blockIdx.x * 128 + threadIdx.x) << 2;   // 512 blocks x 128 thr
    float4 s = *(const float4*)(g_wop + idx);
    #pragma unroll
    for (int z = 1; z < 8; z++) {
        float4 a = *(const float4*)(g_wop + (size_t)z * 262144 + idx);
        s.x += a.x; s.y += a.y; s.z += a.z; s.w += a.w;
    }
    *(float4*)(out + idx) = s;
}

// ---------------- K2: rmsnorm + rope(table) + split ----------------
__global__ void normrope_kernel(const float* __restrict__ q_scale,
                                const float* __restrict__ k_scale)
{
    int slot = blockIdx.x;
    int m    = blockIdx.y;
    int tid  = threadIdx.x;

    int cbase, type, gi = 0;
    if (slot < 16)      { cbase = slot * 128;               type = 0; }
    else if (slot < 20) { cbase = 2048 + (slot - 16) * 128; type = 1; gi = slot - 16; }
    else                { cbase = 2560 + (slot - 20) * 128; type = 2; gi = slot - 20; }

    int idx = m * 3072 + cbase + tid;
    float x = 0.f;
    #pragma unroll
    for (int z = 0; z < QKV_SPLITK; z++)
        x += g_qkvp[z * 393216 + idx];

    if (type == 2) {   // V: no norm, no rope
        g_vn[(m * G_ + gi) * K_ + tid] = x;
        return;
    }

    __shared__ float wsum[4];
    __shared__ float sx[128];

    float ss = x * x;
    #pragma unroll
    for (int o = 16; o; o >>= 1) ss += __shfl_xor_sync(0xffffffffu, ss, o);
    if ((tid & 31) == 0) wsum[tid >> 5] = ss;
    __syncthreads();
    float var = (wsum[0] + wsum[1] + wsum[2] + wsum[3]) * (1.0f / 128.0f);

    float sc = (type == 0) ? q_scale[tid] : k_scale[tid];
    float xn = x * rsqrtf(var + EPS_) * sc;
    sx[tid] = xn;
    __syncthreads();

    int   j  = tid & 63;
    float sv = g_ropes[m * 64 + j];
    float cv = g_ropec[m * 64 + j];

    float out = (tid < 64) ? (sx[j] * cv - sx[j + 64] * sv)
                           : (sx[j + 64] * cv + sx[j] * sv);

    if (type == 0) g_q [(m * H_ + slot) * K_ + tid] = out;
    else           g_kn[(m * G_ + gi)  * K_ + tid] = out;
}

// ---------------- K3: split flash attention, tf32 mma, deep pipeline ---------
// dyn smem floats: KS[2][64*132] | VS[64*136] | P[16*68] | M/L/F[48]
#define ATTN_SMEM_FLOATS (16896 + 8704 + 1088 + 48)
#define ATTN_SMEM_BYTES  (ATTN_SMEM_FLOATS * 4)

__global__ __launch_bounds__(256, 2) void attn_kernel(
    const float* __restrict__ kc,
    const float* __restrict__ vc,
    const int*   __restrict__ seg,
    const int*   __restrict__ curp)
{
    extern __shared__ float smf[];
    float* KS0  = smf;                 // KS[buf] = smf + buf*8448
    float* VS   = smf + 16896;
    float* P    = VS + 8704;
    float* SM_M = P + 1088;
    float* SM_L = SM_M + 16;
    float* SM_F = SM_L + 16;

    int b  = blockIdx.x;
    int g  = blockIdx.y;
    int sp = blockIdx.z;
    int tid  = threadIdx.x;            // 256
    int w    = tid >> 5;
    int lane = tid & 31;
    int gq   = lane >> 2;              // mma group id 0..7
    int tg   = lane & 3;               // thread-in-group 0..3

    int cur   = *curp;
    int s_end = cur + T_;

    int sgv0 = seg[b * T_ + 0], sgv1 = seg[b * T_ + 1];
    int sgv2 = seg[b * T_ + 2], sgv3 = seg[b * T_ + 3];

    // inline left-pads
    int start;
    {
        int csum = 0, lp = 0;
        csum += (sgv0 != 0); if (csum == 0) lp++;
        csum += (sgv1 != 0); if (csum == 0) lp++;
        csum += (sgv2 != 0); if (csum == 0) lp++;
        csum += (sgv3 != 0); if (csum == 0) lp++;
        start = lp;
    }

    // chunk range for this split
    int nch  = (s_end + 63) >> 6;
    int per  = (nch + NS - 1) / NS;
    int c_lo = sp * per;
    int c_hi = min(nch, c_lo + per);
    int cst  = max(c_lo, start >> 6);

    uint32_t ksb = (uint32_t)__cvta_generic_to_shared(KS0);
    uint32_t vsb = (uint32_t)__cvta_generic_to_shared(VS);

    auto issueK = [&](int ci) {
        int s0c = ci << 6;
        uint32_t base = ksb + (uint32_t)(ci & 1) * 8448 * 4;
        #pragma unroll
        for (int it = 0; it < 8; it++) {
            int idx = tid + (it << 8);
            int row = idx >> 5;
            int c4  = (idx & 31) << 2;
            int s   = s0c + row;
            const float* src; bool p = true;
            if (s < cur)        src = kc + ((((size_t)(b * S_ + s)) * G_ + g) << 7) + c4;
            else if (s < s_end) src = g_kn + (((b * T_ + (s - cur)) * G_ + g) << 7) + c4;
            else              { src = kc; p = false; }
            cp_async16(base + (uint32_t)(row * 132 + c4) * 4, src, p);
        }
    };
    auto issueV = [&](int ci) {
        int s0c = ci << 6;
        #pragma unroll
        for (int it = 0; it < 8; it++) {
            int idx = tid + (it << 8);
            int row = idx >> 5;
            int c4  = (idx & 31) << 2;
            int s   = s0c + row;
            const float* src; bool p = true;
            if (s < cur)        src = vc + ((((size_t)(b * S_ + s)) * G_ + g) << 7) + c4;
            else if (s < s_end) src = g_vn + (((b * T_ + (s - cur)) * G_ + g) << 7) + c4;
            else              { src = vc; p = false; }
            cp_async16(vsb + (uint32_t)(row * 136 + c4) * 4, src, p);
        }
    };

    // prologue: pending order must be [K(cst), K(cst+1), V(cst)]
    if (cst < c_hi)     issueK(cst);     cp_commit();
    if (cst + 1 < c_hi) issueK(cst + 1); cp_commit();
    if (cst < c_hi)     issueV(cst);     cp_commit();

    if (tid < 16) { SM_M[tid] = -3e38f; SM_L[tid] = 0.f; }

    // convert Q fragments to tf32 registers once (direct from gmem)
    uint32_t qa[16][4];
    {
        int q0i = gq, q1i = gq + 8;
        const float* qp0 = g_q + (((b * T_ + (q0i >> 2)) * H_ + g * NREP + (q0i & 3)) << 7);
        const float* qp1 = g_q + (((b * T_ + (q1i >> 2)) * H_ + g * NREP + (q1i & 3)) << 7);
        #pragma unroll
        for (int ks = 0; ks < 16; ks++) {
            int col = (ks << 3) + tg;
            qa[ks][0] = cvt_tf32(__ldg(qp0 + col));
            qa[ks][1] = cvt_tf32(__ldg(qp1 + col));
            qa[ks][2] = cvt_tf32(__ldg(qp0 + col + 4));
            qa[ks][3] = cvt_tf32(__ldg(qp1 + col + 4));
        }
    }

    // PV accumulators: warp w owns dims [16w, 16w+16), all 16 queries
    float oc[2][4];
    #pragma unroll
    for (int t = 0; t < 2; t++)
        #pragma unroll
        for (int j = 0; j < 4; j++) oc[t][j] = 0.f;

    int n0 = w << 3;                    // logits: this warp's 8 keys
    __syncthreads();                    // SM_M/SM_L visible

    for (int ci = cst; ci < c_hi; ci++) {
        int s0 = ci << 6;
        // pending: [K(ci), K(ci+1), V(ci)]
        cp_wait<2>();                   // K(ci) complete
        __syncthreads();

        // ---- logits: warp computes 16 queries x its 8 keys via mma ----
        {
            const float* KS = KS0 + (ci & 1) * 8448;
            float sc_[4] = {0.f, 0.f, 0.f, 0.f};
            #pragma unroll
            for (int ks = 0; ks < 16; ks++) {
                int col = (ks << 3) + tg;
                uint32_t b0 = cvt_tf32(KS[(n0 + gq) * 132 + col]);
                uint32_t b1 = cvt_tf32(KS[(n0 + gq) * 132 + col + 4]);
                mma_tf32(sc_, qa[ks][0], qa[ks][1], qa[ks][2], qa[ks][3], b0, b1);
            }
            int sl0 = n0 + (tg << 1);
            int sgl0 = s0 + sl0, sgl1 = sgl0 + 1;
            int kv0 = (sgl0 >= start && sgl0 < s_end) ? 1 : 0;
            int kv1 = (sgl1 >= start && sgl1 < s_end) ? 1 : 0;
            int sgv[4] = {sgv0, sgv1, sgv2, sgv3};
            int t0 = gq >> 2, t1 = (gq + 8) >> 2;
            bool ok00 = (sgl0 <= cur + t0) && (kv0 == sgv[t0]);
            bool ok01 = (sgl1 <= cur + t0) && (kv1 == sgv[t0]);
            bool ok10 = (sgl0 <= cur + t1) && (kv0 == sgv[t1]);
            bool ok11 = (sgl1 <= cur + t1) && (kv1 == sgv[t1]);
            P[ gq      * 68 + sl0    ] = ok00 ? sc_[0] * SCALE_ : -3e38f;
            P[ gq      * 68 + sl0 + 1] = ok01 ? sc_[1] * SCALE_ : -3e38f;
            P[(gq + 8) * 68 + sl0    ] = ok10 ? sc_[2] * SCALE_ : -3e38f;
            P[(gq + 8) * 68 + sl0 + 1] = ok11 ? sc_[3] * SCALE_ : -3e38f;
        }
        __syncthreads();                // P written, KS[ci&1] fully consumed

        if (ci + 2 < c_hi) issueK(ci + 2);   // reuses KS[ci&1], now free
        cp_commit();                    // pending: [K(ci+1), V(ci), K(ci+2)]

        // ---- online softmax: warp w owns queries {2w, 2w+1} ----
        #pragma unroll
        for (int j = 0; j < 2; j++) {
            int q = (w << 1) + j;
            float v0 = P[q * 68 + lane];
            float v1 = P[q * 68 + lane + 32];
            float cm = fmaxf(v0, v1);
            #pragma unroll
            for (int o = 16; o; o >>= 1) cm = fmaxf(cm, __shfl_xor_sync(0xffffffffu, cm, o));
            float mold = SM_M[q];
            float mnew = fmaxf(mold, cm);
            float e0 = (v0 < -1e37f) ? 0.f : __expf(v0 - mnew);
            float e1 = (v1 < -1e37f) ? 0.f : __expf(v1 - mnew);
            P[q * 68 + lane]      = e0;
            P[q * 68 + lane + 32] = e1;
            float sum = e0 + e1;
            #pragma unroll
            for (int o = 16; o; o >>= 1) sum += __shfl_xor_sync(0xffffffffu, sum, o);
            if (lane == 0) {
                float f = (mold < -1e37f) ? 0.f : __expf(mold - mnew);
                SM_F[q] = f;
                SM_L[q] = SM_L[q] * f + sum;
                SM_M[q] = mnew;
            }
        }
        cp_wait<1>();                   // V(ci) complete (K(ci+2) may pend)
        __syncthreads();                // exp P + SM_F visible, VS ready

        // ---- PV: warp w, dims 16w..16w+15, all queries, via mma ----
        {
            float f0 = SM_F[gq], f1 = SM_F[gq + 8];
            #pragma unroll
            for (int t = 0; t < 2; t++) {
                oc[t][0] *= f0; oc[t][1] *= f0;
                oc[t][2] *= f1; oc[t][3] *= f1;
            }
            #pragma unroll
            for (int ks = 0; ks < 8; ks++) {
                int kr = (ks << 3) + tg;
                uint32_t a0 = cvt_tf32(P[ gq      * 68 + kr]);
                uint32_t a1 = cvt_tf32(P[(gq + 8) * 68 + kr]);
                uint32_t a2 = cvt_tf32(P[ gq      * 68 + kr + 4]);
                uint32_t a3 = cvt_tf32(P[(gq + 8) * 68 + kr + 4]);
                #pragma unroll
                for (int t = 0; t < 2; t++) {
                    int nd = (w << 4) + (t << 3) + gq;
                    uint32_t b0 = cvt_tf32(VS[kr * 136 + nd]);
                    uint32_t b1 = cvt_tf32(VS[(kr + 4) * 136 + nd]);
                    mma_tf32(oc[t], a0, a1, a2, a3, b0, b1);
                }
            }
        }
        __syncthreads();                // VS fully consumed

        if (ci + 1 < c_hi) issueV(ci + 1);
        cp_commit();                    // pending: [K(ci+1), K(ci+2), V(ci+1)]
    }

    cp_wait<0>();                       // drain any empty tail groups

    // ---- write partials (unnormalized) ----
    {
        int pbase = ((b * G_ + g) * NS + sp) * 16;
        #pragma unroll
        for (int t = 0; t < 2; t++) {
            int col = (w << 4) + (t << 3) + (tg << 1);
            *(float2*)(g_pacc + (size_t)(pbase + gq) * 128 + col)
                = make_float2(oc[t][0], oc[t][1]);
            *(float2*)(g_pacc + (size_t)(pbase + gq + 8) * 128 + col)
                = make_float2(oc[t][2], oc[t][3]);
        }
        if (tid < 16) {
            g_pm[pbase + tid] = SM_M[tid];
            g_pl[pbase + tid] = SM_L[tid];
        }
    }
}

// ---------------- K3b: combine split partials (512 CTAs) ----------------
__global__ void combine_kernel() {
    int bg   = blockIdx.x;             // 0..127 = b*G+g
    int qtr  = blockIdx.y;             // 0..3: which 32 dims
    int tid  = threadIdx.x;            // 256
    int q    = tid >> 4;               // 0..15
    int kb   = ((tid & 15) << 1) + (qtr << 5);   // 2 dims per thread
    int base = bg * NS * 16;

    float m = -3e38f;
    #pragma unroll
    for (int s = 0; s < NS; s++) m = fmaxf(m, g_pm[base + s * 16 + q]);

    float lsum = 0.f;
    float2 o = make_float2(0.f, 0.f);

    #pragma unroll
    for (int s = 0; s < NS; s++) {
        float ms  = g_pm[base + s * 16 + q];
        float wgt = (ms < -1e37f) ? 0.f : __expf(ms - m);
        lsum += wgt * g_pl[base + s * 16 + q];
        float2 x = *(const float2*)(g_pacc + (size_t)(base + s * 16 + q) * 128 + kb);
        o.x = fmaf(wgt, x.x, o.x); o.y = fmaf(wgt, x.y, o.y);
    }
    float inv = (lsum > 0.f) ? (1.0f / lsum) : 0.f;
    int b = bg >> 2, g = bg & 3;
    int t = q >> 2, r = q & 3;
    float* dst = g_attn + (((b * T_ + t) * H_ + g * NREP + r) << 7) + kb;
    *(float2*)dst = make_float2(o.x * inv, o.y * inv);
}

// ---------------- host launch ----------------
extern "C" void kernel_launch(void* const* d_in, const int* in_sizes, int n_in,
                              void* d_out, int out_size) {
    const float* hidden = (const float*)d_in[0];
    const int*   seg    = (const int*)  d_in[1];
    const float* kc     = (const float*)d_in[2];
    const float* vc     = (const float*)d_in[3];
    const float* Wq     = (const float*)d_in[4];
    const float* Wk     = (const float*)d_in[5];
    const float* Wv     = (const float*)d_in[6];
    const float* Wo     = (const float*)d_in[7];
    const float* qsc    = (const float*)d_in[8];
    const float* ksc    = (const float*)d_in[9];
    const int*   curp   = (const int*)  d_in[10];

    (void)in_sizes; (void)n_in; (void)out_size;

    rope_table_kernel<<<32, 256>>>(seg, curp);
    mma_gemm_kernel<16><<<dim3(48, 2, QKV_SPLITK), 128>>>(hidden, Wq, Wk, Wv, 3072, 1);
    normrope_kernel<<<dim3(24, 128), 128>>>(qsc, ksc);
    cudaFuncSetAttribute(attn_kernel, cudaFuncAttributeMaxDynamicSharedMemorySize,
                         ATTN_SMEM_BYTES);
    attn_kernel<<<dim3(B_, G_, NS), 256, ATTN_SMEM_BYTES>>>(kc, vc, seg, curp);
    combine_kernel<<<dim3(128, 4), 256>>>();
    mma_gemm_kernel<16><<<dim3(32, 2, 8), 128>>>(nullptr, Wo, Wo, Wo, 2048, 0);
    wo_reduce_kernel<<<512, 128>>>((float*)d_out);
}

// round 17
// speedup vs baseline: 1.1226x; 1.1226x over previous
#include <cuda_runtime.h>
#include <cuda_bf16.h>
#include <stdint.h>
#include <stddef.h>

// Problem constants
#define B_   32
#define T_   4
#define D_   2048
#define H_   16
#define G_   4
#define K_   128
#define S_   4096
#define NREP 4
#define NS   7            // sequence splits for attention (49 chunks / 7 = balanced)
#define QKV_SPLITK 4
#define SCALE_ 0.08838834764831845f   // K^-0.5
#define EPS_   1e-6f

// ---------------- device scratch (no allocations allowed) ----------------
__device__ __align__(16) float g_qkvp[QKV_SPLITK * 128 * 3072];  // QKV split-K partials
__device__ __align__(16) float g_wop [8 * 128 * 2048];  // Wo split-K partials
__device__ __align__(16) float g_q  [128 * H_ * K_];    // post norm+rope
__device__ __align__(16) float g_kn [128 * G_ * K_];    // new K rows
__device__ __align__(16) float g_vn [128 * G_ * K_];    // new V rows
__device__ __align__(16) float g_attn[128 * H_ * K_];   // attention out
__device__ float g_ropes[128 * 64];                     // rope sin table [m][j]
__device__ float g_ropec[128 * 64];                     // rope cos table [m][j]
// split-attention partials
__device__ __align__(16) float g_pacc[B_ * G_ * NS * 16 * 128];
__device__ float g_pm  [B_ * G_ * NS * 16];
__device__ float g_pl  [B_ * G_ * NS * 16];

// ---------------- cp.async helpers ----------------
__device__ __forceinline__ void cp_async16(uint32_t dst, const void* src, bool p) {
    asm volatile("cp.async.cg.shared.global [%0], [%1], 16, %2;\n"
                 :: "r"(dst), "l"(src), "r"(p ? 16 : 0));
}
__device__ __forceinline__ void cp_commit() {
    asm volatile("cp.async.commit_group;\n" ::);
}
template<int N> __device__ __forceinline__ void cp_wait() {
    asm volatile("cp.async.wait_group %0;\n" :: "n"(N));
}

// ---------------- tf32 mma helpers ----------------
__device__ __forceinline__ uint32_t cvt_tf32(float x) {
    uint32_t u;
    asm("cvt.rna.tf32.f32 %0, %1;" : "=r"(u) : "f"(x));
    return u;
}
__device__ __forceinline__ void mma_tf32(float c[4],
    uint32_t a0, uint32_t a1, uint32_t a2, uint32_t a3,
    uint32_t b0, uint32_t b1)
{
    asm volatile(
        "mma.sync.aligned.m16n8k8.row.col.f32.tf32.tf32.f32 "
        "{%0,%1,%2,%3}, {%4,%5,%6,%7}, {%8,%9}, {%0,%1,%2,%3};\n"
        : "+f"(c[0]), "+f"(c[1]), "+f"(c[2]), "+f"(c[3])
        : "r"(a0), "r"(a1), "r"(a2), "r"(a3), "r"(b0), "r"(b1));
}

// ---------------- K0: rope sin/cos table (identical math to reference) ------
__global__ void rope_table_kernel(const int* __restrict__ seg,
                                  const int* __restrict__ curp)
{
    int idx = blockIdx.x * 256 + threadIdx.x;   // 0..8191
    if (idx >= 128 * 64) return;
    int m = idx >> 6;
    int j = idx & 63;

    int bb = m >> 2, tt = m & 3;
    int csum = 0;
    #pragma unroll
    for (int t = 0; t < T_; t++)
        if (t <= tt) csum += (seg[bb * T_ + t] != 0) ? 1 : 0;
    int pos = csum - 1 + *curp;

    float fr  = (float)j * (1.0f / 64.0f);
    float ts  = powf(10000.0f, fr);        // accurate pow (matches reference)
    float ang = (float)pos / ts;
    float sv, cv;
    sincosf(ang, &sv, &cv);
    g_ropes[idx] = sv;
    g_ropec[idx] = cv;
}

// ---------------- GEMM: tf32 mma, 64x64 tile, split-K via blockIdx.z ---------
template<int KIT>
__global__ __launch_bounds__(128) void mma_gemm_kernel(
    const float* __restrict__ A_,
    const float* __restrict__ W0, const float* __restrict__ W1,
    const float* __restrict__ W2,
    int ldc, int qkv)
{
    __shared__ alignas(16) float As[4][64][20];   // [buf][m][k], stride 20
    __shared__ alignas(16) float Ws[4][16][72];   // [buf][k][n], stride 72

    const float* A = qkv ? A_ : (const float*)g_attn;
    float*       C = qkv ? (g_qkvp + (size_t)blockIdx.z * 128 * 3072)
                         : (g_wop  + (size_t)blockIdx.z * 128 * 2048);
    int kbase = blockIdx.z * KIT;

    int c0 = blockIdx.x * 64;
    const float* W; int ldb, cb;
    if (qkv) {
        if (c0 < 2048)      { W = W0; ldb = 2048; cb = c0; }
        else if (c0 < 2560) { W = W1; ldb = 512;  cb = c0 - 2048; }
        else                { W = W2; ldb = 512;  cb = c0 - 2560; }
    } else                  { W = W0; ldb = 2048; cb = c0; }

    int m0   = blockIdx.y * 64;
    int tid  = threadIdx.x;           // 128
    int wid  = tid >> 5;
    int lane = tid & 31;
    int gq   = lane >> 2;             // group id 0..7
    int tg   = lane & 3;              // thread-in-group 0..3
    int wm0  = (wid >> 1) << 5;       // warp m offset 0/32
    int wn0  = (wid & 1) << 5;        // warp n offset 0/32

    uint32_t sAs = (uint32_t)__cvta_generic_to_shared(&As[0][0][0]);
    uint32_t sWs = (uint32_t)__cvta_generic_to_shared(&Ws[0][0][0]);

    auto issue = [&](int it, int buf) {
        int k0 = (kbase + it) << 4;
        #pragma unroll
        for (int j = 0; j < 2; j++) {                // A: 64 rows x 16 cols
            int idx = tid + (j << 7);                // 0..255 float4
            int row = idx >> 2, q = (idx & 3) << 2;
            cp_async16(sAs + (uint32_t)(buf * 1280 + row * 20 + q) * 4,
                       A + (size_t)(m0 + row) * 2048 + k0 + q, true);
        }
        #pragma unroll
        for (int j = 0; j < 2; j++) {                // W: 16 rows x 64 cols
            int idx = tid + (j << 7);                // 0..255 float4
            int row = idx >> 4, q = (idx & 15) << 2;
            cp_async16(sWs + (uint32_t)(buf * 1152 + row * 72 + q) * 4,
                       W + (size_t)(k0 + row) * ldb + cb + q, true);
        }
    };

    float c[2][4][4];
    #pragma unroll
    for (int mb = 0; mb < 2; mb++)
        #pragma unroll
        for (int nb = 0; nb < 4; nb++)
            #pragma unroll
            for (int j = 0; j < 4; j++) c[mb][nb][j] = 0.f;

    issue(0, 0); cp_commit();
    issue(1, 1); cp_commit();
    issue(2, 2); cp_commit();

    for (int it = 0; it < KIT; it++) {
        int bf = it & 3;
        cp_wait<2>();
        __syncthreads();

        #pragma unroll
        for (int kk = 0; kk < 16; kk += 8) {
            uint32_t a[2][4], bfr[4][2];
            #pragma unroll
            for (int mb = 0; mb < 2; mb++) {
                int r0 = wm0 + (mb << 4) + gq;
                a[mb][0] = cvt_tf32(As[bf][r0    ][kk + tg]);
                a[mb][1] = cvt_tf32(As[bf][r0 + 8][kk + tg]);
                a[mb][2] = cvt_tf32(As[bf][r0    ][kk + tg + 4]);
                a[mb][3] = cvt_tf32(As[bf][r0 + 8][kk + tg + 4]);
            }
            #pragma unroll
            for (int nb = 0; nb < 4; nb++) {
                int cn = wn0 + (nb << 3) + gq;
                bfr[nb][0] = cvt_tf32(Ws[bf][kk + tg    ][cn]);
                bfr[nb][1] = cvt_tf32(Ws[bf][kk + tg + 4][cn]);
            }
            #pragma unroll
            for (int mb = 0; mb < 2; mb++)
                #pragma unroll
                for (int nb = 0; nb < 4; nb++)
                    mma_tf32(c[mb][nb], a[mb][0], a[mb][1], a[mb][2], a[mb][3],
                             bfr[nb][0], bfr[nb][1]);
        }
        __syncthreads();
        if (it + 3 < KIT) issue(it + 3, (it + 3) & 3);
        cp_commit();
    }

    #pragma unroll
    for (int mb = 0; mb < 2; mb++)
        #pragma unroll
        for (int nb = 0; nb < 4; nb++) {
            int row = m0 + wm0 + (mb << 4) + gq;
            int col = c0 + wn0 + (nb << 3) + (tg << 1);
            *(float2*)(C + (size_t)row * ldc + col)
                = make_float2(c[mb][nb][0], c[mb][nb][1]);
            *(float2*)(C + (size_t)(row + 8) * ldc + col)
                = make_float2(c[mb][nb][2], c[mb][nb][3]);
        }
}

// ---------------- Wo split-K reduce: d_out = sum of 8 partials ----------------
__global__ void wo_reduce_kernel(float* __restrict__ out) {
    int idx = (blockIdx.x * 128 + threadIdx.x) << 2;   // 512 blocks x 128 thr
    float4 s = *(const float4*)(g_wop + idx);
    #pragma unroll
    for (int z = 1; z < 8; z++) {
        float4 a = *(const float4*)(g_wop + (size_t)z * 262144 + idx);
        s.x += a.x; s.y += a.y; s.z += a.z; s.w += a.w;
    }
    *(float4*)(out + idx) = s;
}

// ---------------- K2: rmsnorm + rope(table) + split ----------------
__global__ void normrope_kernel(const float* __restrict__ q_scale,
                                const float* __restrict__ k_scale)
{
    int slot = blockIdx.x;
    int m    = blockIdx.y;
    int tid  = threadIdx.x;

    int cbase, type, gi = 0;
    if (slot < 16)      { cbase = slot * 128;               type = 0; }
    else if (slot < 20) { cbase = 2048 + (slot - 16) * 128; type = 1; gi = slot - 16; }
    else                { cbase = 2560 + (slot - 20) * 128; type = 2; gi = slot - 20; }

    int idx = m * 3072 + cbase + tid;
    float x = 0.f;
    #pragma unroll
    for (int z = 0; z < QKV_SPLITK; z++)
        x += g_qkvp[z * 393216 + idx];

    if (type == 2) {   // V: no norm, no rope
        g_vn[(m * G_ + gi) * K_ + tid] = x;
        return;
    }

    __shared__ float wsum[4];
    __shared__ float sx[128];

    float ss = x * x;
    #pragma unroll
    for (int o = 16; o; o >>= 1) ss += __shfl_xor_sync(0xffffffffu, ss, o);
    if ((tid & 31) == 0) wsum[tid >> 5] = ss;
    __syncthreads();
    float var = (wsum[0] + wsum[1] + wsum[2] + wsum[3]) * (1.0f / 128.0f);

    float sc = (type == 0) ? q_scale[tid] : k_scale[tid];
    float xn = x * rsqrtf(var + EPS_) * sc;
    sx[tid] = xn;
    __syncthreads();

    int   j  = tid & 63;
    float sv = g_ropes[m * 64 + j];
    float cv = g_ropec[m * 64 + j];

    float out = (tid < 64) ? (sx[j] * cv - sx[j + 64] * sv)
                           : (sx[j + 64] * cv + sx[j] * sv);

    if (type == 0) g_q [(m * H_ + slot) * K_ + tid] = out;
    else           g_kn[(m * G_ + gi)  * K_ + tid] = out;
}

// ---------------- K3: split flash attention, tf32 mma, deep pipeline ---------
// dyn smem floats: KS[2][64*132] | VS[64*136] | P[16*68] | M/L/F[48]
#define ATTN_SMEM_FLOATS (16896 + 8704 + 1088 + 48)
#define ATTN_SMEM_BYTES  (ATTN_SMEM_FLOATS * 4)

__global__ __launch_bounds__(256, 2) void attn_kernel(
    const float* __restrict__ kc,
    const float* __restrict__ vc,
    const int*   __restrict__ seg,
    const int*   __restrict__ curp)
{
    extern __shared__ float smf[];
    float* KS0  = smf;                 // KS[buf] = smf + buf*8448
    float* VS   = smf + 16896;
    float* P    = VS + 8704;
    float* SM_M = P + 1088;
    float* SM_L = SM_M + 16;
    float* SM_F = SM_L + 16;

    int b  = blockIdx.x;
    int g  = blockIdx.y;
    int sp = blockIdx.z;
    int tid  = threadIdx.x;            // 256
    int w    = tid >> 5;
    int lane = tid & 31;
    int gq   = lane >> 2;              // mma group id 0..7
    int tg   = lane & 3;               // thread-in-group 0..3

    int cur   = *curp;
    int s_end = cur + T_;

    int sgv0 = seg[b * T_ + 0], sgv1 = seg[b * T_ + 1];
    int sgv2 = seg[b * T_ + 2], sgv3 = seg[b * T_ + 3];

    // inline left-pads
    int start;
    {
        int csum = 0, lp = 0;
        csum += (sgv0 != 0); if (csum == 0) lp++;
        csum += (sgv1 != 0); if (csum == 0) lp++;
        csum += (sgv2 != 0); if (csum == 0) lp++;
        csum += (sgv3 != 0); if (csum == 0) lp++;
        start = lp;
    }

    // chunk range for this split
    int nch  = (s_end + 63) >> 6;
    int per  = (nch + NS - 1) / NS;
    int c_lo = sp * per;
    int c_hi = min(nch, c_lo + per);
    int cst  = max(c_lo, start >> 6);

    uint32_t ksb = (uint32_t)__cvta_generic_to_shared(KS0);
    uint32_t vsb = (uint32_t)__cvta_generic_to_shared(VS);

    // per-thread staging coordinates (fixed)
    int rowt = tid >> 5;               // base row 0..7 (advances by 8 per pass)
    int c4s  = (tid & 31) << 2;        // float4 column
    // fast-path base pointers: s = ci*64 + rowt + it*8, all rows from cache
    const float* kfast = kc + ((size_t)(b * S_) * G_ + g) * K_ + (size_t)rowt * (G_ * K_) + c4s;
    const float* vfast = vc + ((size_t)(b * S_) * G_ + g) * K_ + (size_t)rowt * (G_ * K_) + c4s;

    auto issueK = [&](int ci) {
        uint32_t base = ksb + (uint32_t)(ci & 1) * 8448 * 4;
        if ((ci << 6) + 64 <= cur) {               // fast path: pure cache rows
            const float* src = kfast + (size_t)(ci << 6) * (G_ * K_);
            #pragma unroll
            for (int it = 0; it < 8; it++)
                cp_async16(base + (uint32_t)((rowt + (it << 3)) * 132 + c4s) * 4,
                           src + (size_t)it * 8 * (G_ * K_), true);
        } else {                                   // boundary chunk (once per grid)
            int s0c = ci << 6;
            #pragma unroll
            for (int it = 0; it < 8; it++) {
                int row = rowt + (it << 3);
                int s   = s0c + row;
                const float* src; bool p = true;
                if (s < cur)        src = kc + ((((size_t)(b * S_ + s)) * G_ + g) << 7) + c4s;
                else if (s < s_end) src = g_kn + (((b * T_ + (s - cur)) * G_ + g) << 7) + c4s;
                else              { src = kc; p = false; }
                cp_async16(base + (uint32_t)(row * 132 + c4s) * 4, src, p);
            }
        }
    };
    auto issueV = [&](int ci) {
        if ((ci << 6) + 64 <= cur) {               // fast path
            const float* src = vfast + (size_t)(ci << 6) * (G_ * K_);
            #pragma unroll
            for (int it = 0; it < 8; it++)
                cp_async16(vsb + (uint32_t)((rowt + (it << 3)) * 136 + c4s) * 4,
                           src + (size_t)it * 8 * (G_ * K_), true);
        } else {
            int s0c = ci << 6;
            #pragma unroll
            for (int it = 0; it < 8; it++) {
                int row = rowt + (it << 3);
                int s   = s0c + row;
                const float* src; bool p = true;
                if (s < cur)        src = vc + ((((size_t)(b * S_ + s)) * G_ + g) << 7) + c4s;
                else if (s < s_end) src = g_vn + (((b * T_ + (s - cur)) * G_ + g) << 7) + c4s;
                else              { src = vc; p = false; }
                cp_async16(vsb + (uint32_t)(row * 136 + c4s) * 4, src, p);
            }
        }
    };

    // prologue: pending order must be [K(cst), K(cst+1), V(cst)]
    if (cst < c_hi)     issueK(cst);     cp_commit();
    if (cst + 1 < c_hi) issueK(cst + 1); cp_commit();
    if (cst < c_hi)     issueV(cst);     cp_commit();

    if (tid < 16) { SM_M[tid] = -3e38f; SM_L[tid] = 0.f; }

    // convert Q fragments to tf32 registers once (direct from gmem)
    uint32_t qa[16][4];
    {
        int q0i = gq, q1i = gq + 8;
        const float* qp0 = g_q + (((b * T_ + (q0i >> 2)) * H_ + g * NREP + (q0i & 3)) << 7);
        const float* qp1 = g_q + (((b * T_ + (q1i >> 2)) * H_ + g * NREP + (q1i & 3)) << 7);
        #pragma unroll
        for (int ks = 0; ks < 16; ks++) {
            int col = (ks << 3) + tg;
            qa[ks][0] = cvt_tf32(__ldg(qp0 + col));
            qa[ks][1] = cvt_tf32(__ldg(qp1 + col));
            qa[ks][2] = cvt_tf32(__ldg(qp0 + col + 4));
            qa[ks][3] = cvt_tf32(__ldg(qp1 + col + 4));
        }
    }

    // PV accumulators: warp w owns dims [16w, 16w+16), all 16 queries
    float oc[2][4];
    #pragma unroll
    for (int t = 0; t < 2; t++)
        #pragma unroll
        for (int j = 0; j < 4; j++) oc[t][j] = 0.f;

    int n0 = w << 3;                    // logits: this warp's 8 keys
    __syncthreads();                    // SM_M/SM_L visible

    for (int ci = cst; ci < c_hi; ci++) {
        int s0 = ci << 6;
        // pending: [K(ci), K(ci+1), V(ci)]
        cp_wait<2>();                   // K(ci) complete
        __syncthreads();

        // ---- logits: warp computes 16 queries x its 8 keys via mma ----
        {
            const float* KS = KS0 + (ci & 1) * 8448;
            float sc_[4] = {0.f, 0.f, 0.f, 0.f};
            #pragma unroll
            for (int ks = 0; ks < 16; ks++) {
                int col = (ks << 3) + tg;
                uint32_t b0 = cvt_tf32(KS[(n0 + gq) * 132 + col]);
                uint32_t b1 = cvt_tf32(KS[(n0 + gq) * 132 + col + 4]);
                mma_tf32(sc_, qa[ks][0], qa[ks][1], qa[ks][2], qa[ks][3], b0, b1);
            }
            int sl0 = n0 + (tg << 1);
            int sgl0 = s0 + sl0, sgl1 = sgl0 + 1;
            int kv0 = (sgl0 >= start && sgl0 < s_end) ? 1 : 0;
            int kv1 = (sgl1 >= start && sgl1 < s_end) ? 1 : 0;
            int sgv[4] = {sgv0, sgv1, sgv2, sgv3};
            int t0 = gq >> 2, t1 = (gq + 8) >> 2;
            bool ok00 = (sgl0 <= cur + t0) && (kv0 == sgv[t0]);
            bool ok01 = (sgl1 <= cur + t0) && (kv1 == sgv[t0]);
            bool ok10 = (sgl0 <= cur + t1) && (kv0 == sgv[t1]);
            bool ok11 = (sgl1 <= cur + t1) && (kv1 == sgv[t1]);
            P[ gq      * 68 + sl0    ] = ok00 ? sc_[0] * SCALE_ : -3e38f;
            P[ gq      * 68 + sl0 + 1] = ok01 ? sc_[1] * SCALE_ : -3e38f;
            P[(gq + 8) * 68 + sl0    ] = ok10 ? sc_[2] * SCALE_ : -3e38f;
            P[(gq + 8) * 68 + sl0 + 1] = ok11 ? sc_[3] * SCALE_ : -3e38f;
        }
        __syncthreads();                // P written, KS[ci&1] fully consumed

        if (ci + 2 < c_hi) issueK(ci + 2);   // reuses KS[ci&1], now free
        cp_commit();                    // pending: [K(ci+1), V(ci), K(ci+2)]

        // ---- online softmax: warp w owns queries {2w, 2w+1} ----
        #pragma unroll
        for (int j = 0; j < 2; j++) {
            int q = (w << 1) + j;
            float v0 = P[q * 68 + lane];
            float v1 = P[q * 68 + lane + 32];
            float cm = fmaxf(v0, v1);
            #pragma unroll
            for (int o = 16; o; o >>= 1) cm = fmaxf(cm, __shfl_xor_sync(0xffffffffu, cm, o));
            float mold = SM_M[q];
            float mnew = fmaxf(mold, cm);
            float e0 = (v0 < -1e37f) ? 0.f : __expf(v0 - mnew);
            float e1 = (v1 < -1e37f) ? 0.f : __expf(v1 - mnew);
            P[q * 68 + lane]      = e0;
            P[q * 68 + lane + 32] = e1;
            float sum = e0 + e1;
            #pragma unroll
            for (int o = 16; o; o >>= 1) sum += __shfl_xor_sync(0xffffffffu, sum, o);
            if (lane == 0) {
                float f = (mold < -1e37f) ? 0.f : __expf(mold - mnew);
                SM_F[q] = f;
                SM_L[q] = SM_L[q] * f + sum;
                SM_M[q] = mnew;
            }
        }
        cp_wait<1>();                   // V(ci) complete (K(ci+2) may pend)
        __syncthreads();                // exp P + SM_F visible, VS ready

        // ---- PV: warp w, dims 16w..16w+15, all queries, via mma ----
        // raw fp32 bits as tf32 operands (HW truncates mantissa; RZ rounding)
        {
            float f0 = SM_F[gq], f1 = SM_F[gq + 8];
            #pragma unroll
            for (int t = 0; t < 2; t++) {
                oc[t][0] *= f0; oc[t][1] *= f0;
                oc[t][2] *= f1; oc[t][3] *= f1;
            }
            #pragma unroll
            for (int ks = 0; ks < 8; ks++) {
                int kr = (ks << 3) + tg;
                uint32_t a0 = __float_as_uint(P[ gq      * 68 + kr]);
                uint32_t a1 = __float_as_uint(P[(gq + 8) * 68 + kr]);
                uint32_t a2 = __float_as_uint(P[ gq      * 68 + kr + 4]);
                uint32_t a3 = __float_as_uint(P[(gq + 8) * 68 + kr + 4]);
                #pragma unroll
                for (int t = 0; t < 2; t++) {
                    int nd = (w << 4) + (t << 3) + gq;
                    uint32_t b0 = __float_as_uint(VS[kr * 136 + nd]);
                    uint32_t b1 = __float_as_uint(VS[(kr + 4) * 136 + nd]);
                    mma_tf32(oc[t], a0, a1, a2, a3, b0, b1);
                }
            }
        }
        __syncthreads();                // VS fully consumed

        if (ci + 1 < c_hi) issueV(ci + 1);
        cp_commit();                    // pending: [K(ci+1), K(ci+2), V(ci+1)]
    }

    cp_wait<0>();                       // drain any empty tail groups

    // ---- write partials (unnormalized) ----
    {
        int pbase = ((b * G_ + g) * NS + sp) * 16;
        #pragma unroll
        for (int t = 0; t < 2; t++) {
            int col = (w << 4) + (t << 3) + (tg << 1);
            *(float2*)(g_pacc + (size_t)(pbase + gq) * 128 + col)
                = make_float2(oc[t][0], oc[t][1]);
            *(float2*)(g_pacc + (size_t)(pbase + gq + 8) * 128 + col)
                = make_float2(oc[t][2], oc[t][3]);
        }
        if (tid < 16) {
            g_pm[pbase + tid] = SM_M[tid];
            g_pl[pbase + tid] = SM_L[tid];
        }
    }
}

// ---------------- K3b: combine split partials (512 CTAs) ----------------
__global__ void combine_kernel() {
    int bg   = blockIdx.x;             // 0..127 = b*G+g
    int qtr  = blockIdx.y;             // 0..3: which 32 dims
    int tid  = threadIdx.x;            // 256
    int q    = tid >> 4;               // 0..15
    int kb   = ((tid & 15) << 1) + (qtr << 5);   // 2 dims per thread
    int base = bg * NS * 16;

    float m = -3e38f;
    #pragma unroll
    for (int s = 0; s < NS; s++) m = fmaxf(m, g_pm[base + s * 16 + q]);

    float lsum = 0.f;
    float2 o = make_float2(0.f, 0.f);

    #pragma unroll
    for (int s = 0; s < NS; s++) {
        float ms  = g_pm[base + s * 16 + q];
        float wgt = (ms < -1e37f) ? 0.f : __expf(ms - m);
        lsum += wgt * g_pl[base + s * 16 + q];
        float2 x = *(const float2*)(g_pacc + (size_t)(base + s * 16 + q) * 128 + kb);
        o.x = fmaf(wgt, x.x, o.x); o.y = fmaf(wgt, x.y, o.y);
    }
    float inv = (lsum > 0.f) ? (1.0f / lsum) : 0.f;
    int b = bg >> 2, g = bg & 3;
    int t = q >> 2, r = q & 3;
    float* dst = g_attn + (((b * T_ + t) * H_ + g * NREP + r) << 7) + kb;
    *(float2*)dst = make_float2(o.x * inv, o.y * inv);
}

// ---------------- host launch ----------------
extern "C" void kernel_launch(void* const* d_in, const int* in_sizes, int n_in,
                              void* d_out, int out_size) {
    const float* hidden = (const float*)d_in[0];
    const int*   seg    = (const int*)  d_in[1];
    const float* kc     = (const float*)d_in[2];
    const float* vc     = (const float*)d_in[3];
    const float* Wq     = (const float*)d_in[4];
    const float* Wk     = (const float*)d_in[5];
    const float* Wv     = (const float*)d_in[6];
    const float* Wo     = (const float*)d_in[7];
    const float* qsc    = (const float*)d_in[8];
    const float* ksc    = (const float*)d_in[9];
    const int*   curp   = (const int*)  d_in[10];

    (void)in_sizes; (void)n_in; (void)out_size;

    rope_table_kernel<<<32, 256>>>(seg, curp);
    mma_gemm_kernel<32><<<dim3(48, 2, QKV_SPLITK), 128>>>(hidden, Wq, Wk, Wv, 3072, 1);
    normrope_kernel<<<dim3(24, 128), 128>>>(qsc, ksc);
    cudaFuncSetAttribute(attn_kernel, cudaFuncAttributeMaxDynamicSharedMemorySize,
                         ATTN_SMEM_BYTES);
    attn_kernel<<<dim3(B_, G_, NS), 256, ATTN_SMEM_BYTES>>>(kc, vc, seg, curp);
    combine_kernel<<<dim3(128, 4), 256>>>();
    mma_gemm_kernel<16><<<dim3(32, 2, 8), 128>>>(nullptr, Wo, Wo, Wo, 2048, 0);
    wo_reduce_kernel<<<512, 128>>>((float*)d_out);
}